// round 9
// baseline (speedup 1.0000x reference)
#include <cuda_runtime.h>
#include <cuda_fp16.h>
#include <math.h>

#define NN   200
#define DEGN 199
#define KK   20
#define MMg  10
#define HIDN 96
#define NHh  4
#define HDd  118
#define DMm  472
#define AJRn 30

#define S_OFF  0
#define H_OFF  18880000
#define HF_OFF 18899200
#define Q_OFF  18922800

#define GCN_MAX_IT 4

// ---------------- static device scratch ----------------
__device__ float g_stat[NN*HIDN];
__device__ float g_den1[NN], g_den2[NN];
__device__ float g_hA[NN*HIDN], g_hB[NN*HIDN];
__device__ float g_hfull[NN*HDd];
__device__ float g_gcT[KK*HDd];
__device__ float g_lg[NN*HDd];
__device__ float g_W0s[HDd*DMm], g_W1s[HDd*DMm];
__device__ float g_P1[NN*DMm], g_P2[NN*DMm];
__device__ float g_khs[NHh*HDd*NN];     // [h][d][k]
__device__ float g_vh[NHh*NN*HDd];      // [h][k][d]
__device__ float g_U[NN*NHh*NN], g_V[NN*NHh*NN];   // [(i*4+h)][k]
__device__ float g_EU[NN*NHh*NN], g_EV[NN*NHh*NN]; // exp(U - rowmax), exp(V - rowmax)
__device__ __half g_VWh[800*DMm];       // [h*200+k][c]  fp16
__device__ __half g_Pch[40000u*800u];   // 64 MB fp16

// ---------------- prep: edge sorts + static part of GCN ----------------
__global__ void k_prep(const float* __restrict__ x, const float* __restrict__ label,
                       const float* __restrict__ h0,
                       const float* __restrict__ w, const float* __restrict__ dv,
                       const float* __restrict__ l0w, const float* __restrict__ l0b,
                       const float* __restrict__ l1w, const float* __restrict__ l1b,
                       const float* __restrict__ l2b, const float* __restrict__ l3b,
                       const float* __restrict__ l4w, const float* __restrict__ l4b,
                       const float* __restrict__ l5w, const float* __restrict__ l5b)
{
    int i = blockIdx.x; int t = threadIdx.x;  // 128 threads
    int gi = i / MMg;
    __shared__ float a1[256], a2[256];
    __shared__ float red1[128], red2[128];
    float p1 = 0.f, p2 = 0.f;
    for (int e = t; e < 256; e += 128) {
        float v1 = -1e30f, v2 = -1e30f;
        if (e < DEGN) {
            int s = (e < i) ? e : e + 1;
            bool sm = (s / MMg) == gi;
            float d0 = dv[i*DEGN + e];
            float w0 = w[i*DEGN + e];
            if (sm) { v2 = d0; p2 += w0; } else { v1 = d0; p1 += w0; }
        }
        a1[e] = v1; a2[e] = v2;
    }
    red1[t] = p1; red2[t] = p2;
    __syncthreads();
    for (int off = 64; off > 0; off >>= 1) {
        if (t < off) { red1[t] += red1[t+off]; red2[t] += red2[t+off]; }
        __syncthreads();
    }
    if (t == 0) { g_den1[i] = red1[0]; g_den2[i] = red2[0]; }
    for (int ksz = 2; ksz <= 256; ksz <<= 1) {
        for (int jsz = ksz >> 1; jsz > 0; jsz >>= 1) {
            __syncthreads();
            for (int e = t; e < 256; e += 128) {
                int p = e ^ jsz;
                if (p > e) {
                    bool desc = ((e & ksz) == 0);
                    float av = a1[e], bv = a1[p];
                    if (desc ? (av < bv) : (av > bv)) { a1[e] = bv; a1[p] = av; }
                    float cv = a2[e], ev = a2[p];
                    if (desc ? (cv < ev) : (cv > ev)) { a2[e] = ev; a2[p] = cv; }
                }
            }
        }
    }
    __syncthreads();
    if (t < HIDN) {
        float acc = l0b[t] + l1b[t] + l2b[t] + l3b[t] + l4b[t] + l5b[t];
        acc += x[i*2+0]*l0w[0*HIDN+t] + x[i*2+1]*l0w[1*HIDN+t];
        for (int g = 0; g < KK; g++) acc += label[i*KK+g]*l1w[g*HIDN+t];
        for (int r = 0; r < AJRn; r++) acc += a1[r]*l4w[r*HIDN+t];
        for (int r = 0; r < MMg-1; r++) acc += a2[r]*l5w[r*HIDN+t];
        g_stat[i*HIDN+t] = acc;
        g_hA[i*HIDN+t] = h0[i*HIDN+t];
    }
}

// ---------------- one GCN iteration (early-exit past gnn_step) ----------------
__global__ void k_gcn(const float* __restrict__ w,
                      const float* __restrict__ l2w, const float* __restrict__ l3w,
                      const int* __restrict__ gnn_step, int iter)
{
    if (!(iter < *gnn_step)) return;
    int i = blockIdx.x, c = threadIdx.x;  // 96 threads
    const float* hin  = (iter & 1) ? g_hB : g_hA;
    float*       hout = (iter & 1) ? g_hA : g_hB;
    int gi = i / MMg;
    float acc1 = 0.f, acc2 = 0.f;
    __shared__ float sn1[HIDN], sn2[HIDN];
    for (int s = 0; s < NN; s++) {
        if (s == i) continue;
        int j = s - (s > i);
        float wv = w[i*DEGN + j];
        float hv = hin[s*HIDN + c];
        if (s / MMg == gi) acc2 += wv*hv; else acc1 += wv*hv;
    }
    sn1[c] = acc1 / g_den1[i];
    sn2[c] = acc2 / g_den2[i];
    __syncthreads();
    float o = g_stat[i*HIDN + c];
    for (int r = 0; r < HIDN; r++)
        o += sn1[r]*l2w[r*HIDN+c] + sn2[r]*l3w[r*HIDN+c];
    hout[i*HIDN + c] = fmaxf(o, 0.f);
}

// ---------------- h_full = [h + pe, x, label]  (parity-select h buffer) ----------------
__global__ void k_hfull(const float* __restrict__ x, const float* __restrict__ label,
                        const int* __restrict__ remain, const int* __restrict__ gnn_step)
{
    int i = blockIdx.x, t = threadIdx.x;
    if (t >= HDd) return;
    int n = *gnn_step; if (n > GCN_MAX_IT) n = GCN_MAX_IT;
    const float* hbuf = (n & 1) ? g_hB : g_hA;
    float v;
    if (t < HIDN) {
        int p = *remain;
        int k2 = t & ~1;
        double div = exp(-(double)k2 * log(10000.0) / (double)HIDN);
        double ang = (double)p * div;
        v = hbuf[i*HIDN + t] + (float)((t & 1) ? cos(ang) : sin(ang));
    } else if (t < HIDN + 2) v = x[i*2 + (t - HIDN)];
    else v = label[i*KK + (t - HIDN - 2)];
    g_hfull[i*HDd + t] = v;
}

__global__ void k_gct(const float* __restrict__ label)
{
    int g = blockIdx.x, dd = threadIdx.x;
    float acc = 0.f;
    for (int i = 0; i < NN; i++) acc += label[i*KK + g] * g_hfull[i*HDd + dd];
    g_gcT[g*HDd + dd] = acc * 0.1f;
}

__global__ void k_lg(const float* __restrict__ label)
{
    int i = blockIdx.x, dd = threadIdx.x;
    float acc = 0.f;
    for (int g = 0; g < KK; g++) acc += label[i*KK + g] * g_gcT[g*HDd + dd];
    g_lg[i*HDd + dd] = acc;
}

__global__ void k_wsum(const float* __restrict__ W0, const float* __restrict__ W1)
{
    int idx = blockIdx.x * blockDim.x + threadIdx.x;
    if (idx >= HDd*DMm) return;
    int d = idx / DMm, c = idx % DMm;
    g_W0s[idx] = W0[d*DMm+c] + W0[(118+d)*DMm+c] + W0[(236+d)*DMm+c] + W0[(354+d)*DMm+c];
    g_W1s[idx] = W1[d*DMm+c] + W1[(118+d)*DMm+c] + W1[(236+d)*DMm+c] + W1[(354+d)*DMm+c];
}

// ---------------- per-node projections ----------------
__global__ void k_proj(const float* __restrict__ W0, const float* __restrict__ B0,
                       const float* __restrict__ B1)
{
    int i = blockIdx.x, t = threadIdx.x;  // 128 threads
    __shared__ float hf[HDd], lgs[HDd];
    if (t < HDd) { hf[t] = g_hfull[i*HDd + t]; lgs[t] = g_lg[i*HDd + t]; }
    __syncthreads();
    const float scale = 1.0f / sqrtf((float)HDd);
    for (int c = t; c < DMm; c += 128) {
        float p1 = B0[c], p2 = 0.f, kf = B0[c], vf = B1[c];
        for (int d = 0; d < HDd; d++) {
            float hv = hf[d], lv = lgs[d];
            p1 += hv * W0[d*DMm + c]       + lv * W0[(236+d)*DMm + c];
            p2 += hv * W0[(118+d)*DMm + c] + lv * W0[(354+d)*DMm + c];
            kf += hv * g_W0s[d*DMm + c];
            vf += hv * g_W1s[d*DMm + c];
        }
        g_P1[i*DMm + c] = p1;
        g_P2[i*DMm + c] = p2;
        int h = c / HDd, dd = c % HDd;
        g_khs[(h*HDd + dd)*NN + i] = kf * scale;
        g_vh[(h*NN + i)*HDd + dd] = vf;
    }
}

// ---------------- U/V score components ----------------
__global__ void k_uv()
{
    int i = blockIdx.x, h = blockIdx.y, t = threadIdx.x;  // 256 threads
    __shared__ float s1[HDd], s2[HDd];
    if (t < HDd) {
        s1[t] = g_P1[i*DMm + h*HDd + t];
        s2[t] = g_P2[i*DMm + h*HDd + t];
    }
    __syncthreads();
    if (t < NN) {
        float u = 0.f, v = 0.f;
        for (int d = 0; d < HDd; d++) {
            float kv = g_khs[(h*HDd + d)*NN + t];
            u += s1[d] * kv;
            v += s2[d] * kv;
        }
        g_U[(i*NHh + h)*NN + t] = u;
        g_V[(i*NHh + h)*NN + t] = v;
    }
}

// ---------------- EU/EV: rowwise exp(x - rowmax) ----------------
__global__ void k_expuv()
{
    int row = blockIdx.x * 8 + (threadIdx.x >> 5);   // 0..799
    int lane = threadIdx.x & 31;
    const float* Ur = g_U + row * NN;
    const float* Vr = g_V + row * NN;
    float u[7], v[7];
    float mu = -1e30f, mv = -1e30f;
    #pragma unroll
    for (int r = 0; r < 7; r++) {
        int k = lane + 32*r;
        if (k < NN) {
            u[r] = Ur[k]; v[r] = Vr[k];
            mu = fmaxf(mu, u[r]); mv = fmaxf(mv, v[r]);
        } else { u[r] = -1e30f; v[r] = -1e30f; }
    }
    #pragma unroll
    for (int o = 16; o > 0; o >>= 1) {
        mu = fmaxf(mu, __shfl_xor_sync(0xffffffffu, mu, o));
        mv = fmaxf(mv, __shfl_xor_sync(0xffffffffu, mv, o));
    }
    #pragma unroll
    for (int r = 0; r < 7; r++) {
        int k = lane + 32*r;
        if (k < NN) {
            g_EU[row * NN + k] = __expf(u[r] - mu);
            g_EV[row * NN + k] = __expf(v[r] - mv);
        }
    }
}

// ---------------- pair-softmax: 2 pairs (same i) per block ----------------
__global__ __launch_bounds__(256) void k_prob()
{
    int b0 = blockIdx.x * 2;
    int i = b0 / NN, j0 = b0 % NN;     // j0 even -> j0+1 < 200
    int w = threadIdx.x >> 5;
    int lane = threadIdx.x & 31;
    int h = w & 3, side = w >> 2;
    __shared__ float s[2][800];

    // side0: p = EU_i * EV_j ; side1: p = EU_j * EV_i
    const float* Ei = side ? (g_EV + (i*NHh + h)*NN) : (g_EU + (i*NHh + h)*NN);
    float a[7];
    #pragma unroll
    for (int r = 0; r < 7; r++) {
        int k = lane + 32*r;
        a[r] = (k < NN) ? Ei[k] : 0.f;
    }

    #pragma unroll
    for (int jj = 0; jj < 2; jj++) {
        int j = j0 + jj;
        const float* Ej = side ? (g_EU + (j*NHh + h)*NN) : (g_EV + (j*NHh + h)*NN);
        float p[7];
        float sum = 0.f;
        #pragma unroll
        for (int r = 0; r < 7; r++) {
            int k = lane + 32*r;
            if (k < NN) { p[r] = a[r] * Ej[k]; sum += p[r]; }
            else p[r] = 0.f;
        }
        #pragma unroll
        for (int o = 16; o > 0; o >>= 1)
            sum += __shfl_xor_sync(0xffffffffu, sum, o);
        float inv = 1.f / sum;

        if (side == 1) {
            #pragma unroll
            for (int r = 0; r < 7; r++) {
                int k = lane + 32*r;
                if (k < NN) s[jj][h*200 + k] = p[r] * inv;
            }
        }
        __syncthreads();
        if (side == 0) {
            #pragma unroll
            for (int r = 0; r < 7; r++) {
                int k = lane + 32*r;
                if (k < NN) s[jj][h*200 + k] = p[r] * inv + s[jj][h*200 + k];
            }
        }
        __syncthreads();
    }
    #pragma unroll
    for (int jj = 0; jj < 2; jj++) {
        __half2* dst = (__half2*)(g_Pch + (size_t)(b0 + jj) * 800);
        for (int t2 = threadIdx.x; t2 < 400; t2 += 256)
            dst[t2] = __floats2half2_rn(s[jj][2*t2], s[jj][2*t2 + 1]);
    }
}

// ---------------- VW (fp16) ----------------
__global__ void k_vw(const float* __restrict__ W3)
{
    int row = blockIdx.x, t = threadIdx.x;  // 128 threads
    int h = row / NN, k = row % NN;
    __shared__ float vr[HDd];
    if (t < HDd) vr[t] = g_vh[(h*NN + k)*HDd + t];
    __syncthreads();
    for (int c = t; c < DMm; c += 128) {
        float acc = 0.f;
        for (int d = 0; d < HDd; d++) acc += vr[d] * W3[(h*HDd + d)*DMm + c];
        g_VWh[row*DMm + c] = __float2half_rn(acc);
    }
}

// ---------------- fp16 MMA GEMM: S = Pc(40000x800) @ VW(800x472) + 2*b3 ----------------
#define BMt 128
#define BNt 64
#define BKt 32
#define A_STRIDE 40
#define B_STRIDE 72
#define A_BYTES  (BMt * A_STRIDE * 2)
#define B_BYTES  (BKt * B_STRIDE * 2)
#define STG_BYTES (A_BYTES + B_BYTES)
#define KT 25

__device__ __forceinline__ void cp_async16(unsigned dst, const void* src, int src_bytes) {
    asm volatile("cp.async.cg.shared.global [%0], [%1], 16, %2;\n"
                 :: "r"(dst), "l"(src), "r"(src_bytes));
}
__device__ __forceinline__ void cp_commit() {
    asm volatile("cp.async.commit_group;\n");
}
__device__ __forceinline__ void cp_wait1() {
    asm volatile("cp.async.wait_group 1;\n");
}
__device__ __forceinline__ void ldmA4(unsigned* r, unsigned addr) {
    asm volatile("ldmatrix.sync.aligned.m8n8.x4.shared.b16 {%0,%1,%2,%3}, [%4];"
                 : "=r"(r[0]), "=r"(r[1]), "=r"(r[2]), "=r"(r[3]) : "r"(addr));
}
__device__ __forceinline__ void ldmBT4(unsigned* r, unsigned addr) {
    asm volatile("ldmatrix.sync.aligned.m8n8.x4.trans.shared.b16 {%0,%1,%2,%3}, [%4];"
                 : "=r"(r[0]), "=r"(r[1]), "=r"(r[2]), "=r"(r[3]) : "r"(addr));
}
__device__ __forceinline__ void mma_f16(float* c, const unsigned* a, const unsigned* b) {
    asm volatile("mma.sync.aligned.m16n8k16.row.col.f32.f16.f16.f32 "
                 "{%0,%1,%2,%3},{%4,%5,%6,%7},{%8,%9},{%0,%1,%2,%3};"
                 : "+f"(c[0]), "+f"(c[1]), "+f"(c[2]), "+f"(c[3])
                 : "r"(a[0]), "r"(a[1]), "r"(a[2]), "r"(a[3]), "r"(b[0]), "r"(b[1]));
}

__device__ __forceinline__ void load_stage(unsigned sbase, int stage, int k0,
                                           int bm, int bn, int t)
{
    unsigned sa = sbase + stage * STG_BYTES;
    unsigned sb = sa + A_BYTES;
    #pragma unroll
    for (int p = 0; p < 2; p++) {
        int li = t + p * 256;
        int row = li >> 2, ch = li & 3;
        int grow = bm + row;
        bool ok = (grow < 40000);
        const __half* src = g_Pch + (size_t)(ok ? grow : 0) * 800 + k0 + ch * 8;
        cp_async16(sa + (unsigned)(row * A_STRIDE + ch * 8) * 2, src, ok ? 16 : 0);
    }
    {
        int k = t >> 3, ch = t & 7;
        int col = bn + ch * 8;
        int rem = DMm - col;
        int sz = (rem >= 8) ? 16 : ((rem > 0) ? rem * 2 : 0);
        const __half* src = g_VWh + (size_t)(k0 + k) * DMm + ((col < DMm) ? col : 0);
        cp_async16(sb + (unsigned)(k * B_STRIDE + ch * 8) * 2, src, sz);
    }
}

__global__ __launch_bounds__(256) void k_mma(const float* __restrict__ B3,
                                             float* __restrict__ out)
{
    __shared__ __align__(16) unsigned char smem[3 * STG_BYTES];
    unsigned sbase = (unsigned)__cvta_generic_to_shared(smem);

    int t = threadIdx.x;
    int w = t >> 5, lane = t & 31;
    int wm = (w & 3) * 32;
    int wn = (w >> 2) * 32;
    int bm = blockIdx.y * BMt, bn = blockIdx.x * BNt;

    float acc[2][4][4];
    #pragma unroll
    for (int mm = 0; mm < 2; mm++)
        #pragma unroll
        for (int nn = 0; nn < 4; nn++)
            #pragma unroll
            for (int q = 0; q < 4; q++) acc[mm][nn][q] = 0.f;

    int arow = wm + (lane & 15);
    int acb  = (lane >> 4) * 8;
    int bkl  = (lane & 7) + (lane & 8);
    int bnl  = wn + ((lane >> 4) * 8);

    load_stage(sbase, 0, 0, bm, bn, t);  cp_commit();
    load_stage(sbase, 1, 32, bm, bn, t); cp_commit();

    for (int kt = 0; kt < KT; kt++) {
        cp_wait1();
        __syncthreads();
        // single sync per iteration: every warp passed the barrier => all reads of
        // stage (kt-1)%3 == (kt+2)%3 are complete, so prefetching into it is safe.
        if (kt + 2 < KT) load_stage(sbase, (kt + 2) % 3, (kt + 2) * BKt, bm, bn, t);
        cp_commit();
        unsigned sa = sbase + (kt % 3) * STG_BYTES;
        unsigned sb = sa + A_BYTES;
        #pragma unroll
        for (int ks = 0; ks < 2; ks++) {
            unsigned af[2][4], bf[2][4];
            ldmA4(af[0], sa + (unsigned)((arow)      * A_STRIDE + ks * 16 + acb) * 2);
            ldmA4(af[1], sa + (unsigned)((arow + 16) * A_STRIDE + ks * 16 + acb) * 2);
            ldmBT4(bf[0], sb + (unsigned)((ks * 16 + bkl) * B_STRIDE + bnl) * 2);
            ldmBT4(bf[1], sb + (unsigned)((ks * 16 + bkl) * B_STRIDE + bnl + 16) * 2);
            #pragma unroll
            for (int mm = 0; mm < 2; mm++) {
                mma_f16(acc[mm][0], af[mm], bf[0] + 0);
                mma_f16(acc[mm][1], af[mm], bf[0] + 2);
                mma_f16(acc[mm][2], af[mm], bf[1] + 0);
                mma_f16(acc[mm][3], af[mm], bf[1] + 2);
            }
        }
    }

    int r0 = bm + wm + (lane >> 2);
    int c0 = bn + wn + (lane & 3) * 2;
    #pragma unroll
    for (int mm = 0; mm < 2; mm++) {
        int rbase = r0 + mm * 16;
        #pragma unroll
        for (int nn = 0; nn < 4; nn++) {
            int c = c0 + nn * 8;
            if (c < DMm) {
                float b3a = 2.f * B3[c], b3b = 2.f * B3[c + 1];
                if (rbase < 40000) {
                    float2 v = make_float2(acc[mm][nn][0] + b3a, acc[mm][nn][1] + b3b);
                    *(float2*)&out[(size_t)rbase * DMm + c] = v;
                }
                if (rbase + 8 < 40000) {
                    float2 v = make_float2(acc[mm][nn][2] + b3a, acc[mm][nn][3] + b3b);
                    *(float2*)&out[(size_t)(rbase + 8) * DMm + c] = v;
                }
            }
        }
    }
}

// ---------------- Q_sa: smem-tiled GEMM, 256 rows/block, 4x12 per thread ----------------
#define QROWS 256
#define QKT   32
__global__ __launch_bounds__(256) void k_qsa(const float* __restrict__ v1w,
                                             const float* __restrict__ v1b,
                                             const float* __restrict__ v2w,
                                             const float* __restrict__ v2b,
                                             const float* __restrict__ S,
                                             float* __restrict__ qout)
{
    __shared__ float sS[QKT][QROWS + 1];
    __shared__ float sW[QKT][48];

    int tid = threadIdx.x;
    int ty = tid >> 2;
    int tx = tid & 3;
    int base = blockIdx.x * QROWS;

    float acc[4][12];
    #pragma unroll
    for (int r = 0; r < 4; r++)
        #pragma unroll
        for (int c = 0; c < 12; c++) acc[r][c] = 0.f;

    for (int k0 = 0; k0 < DMm; k0 += QKT) {
        int TK = DMm - k0; if (TK > QKT) TK = QKT;
        #pragma unroll
        for (int it = 0; it < 8; it++) {
            int idx = tid + it * 256;
            int r = idx >> 3;
            int c4 = idx & 7;
            int k = c4 * 4;
            if (k < TK) {
                int grow = base + r;
                const float* src = S + (size_t)(grow < 40000 ? grow : 0) * DMm + k0 + k;
                float4 v = *(const float4*)src;
                sS[k + 0][r] = v.x; sS[k + 1][r] = v.y;
                sS[k + 2][r] = v.z; sS[k + 3][r] = v.w;
            }
        }
        #pragma unroll
        for (int it = 0; it < 6; it++) {
            int idx = tid + it * 256;
            int k = idx / 48, c = idx - k * 48;
            if (k < TK)
                sW[k][c] = v1w[(k0 + k) * 48 + c];
        }
        __syncthreads();
        for (int k = 0; k < TK; k++) {
            float a0 = sS[k][ty * 4 + 0];
            float a1 = sS[k][ty * 4 + 1];
            float a2 = sS[k][ty * 4 + 2];
            float a3 = sS[k][ty * 4 + 3];
            #pragma unroll
            for (int c = 0; c < 12; c++) {
                float wv = sW[k][tx * 12 + c];
                acc[0][c] += a0 * wv;
                acc[1][c] += a1 * wv;
                acc[2][c] += a2 * wv;
                acc[3][c] += a3 * wv;
            }
        }
        __syncthreads();
    }

    float b1[12], w2[12];
    #pragma unroll
    for (int c = 0; c < 12; c++) {
        b1[c] = v1b[tx * 12 + c];
        w2[c] = v2w[tx * 12 + c];
    }
    float vb2 = v2b[0];
    #pragma unroll
    for (int r = 0; r < 4; r++) {
        float part = 0.f;
        #pragma unroll
        for (int c = 0; c < 12; c++)
            part += fmaxf(acc[r][c] + b1[c], 0.f) * w2[c];
        part += __shfl_xor_sync(0xffffffffu, part, 1);
        part += __shfl_xor_sync(0xffffffffu, part, 2);
        int row = base + ty * 4 + r;
        if (tx == 0 && row < 40000) qout[row] = part + vb2;
    }
}

// ---------------- tail: copy h, h_full into output ----------------
__global__ void k_tail(float* __restrict__ out, const int* __restrict__ gnn_step)
{
    int idx = blockIdx.x * blockDim.x + threadIdx.x;
    int n = *gnn_step; if (n > GCN_MAX_IT) n = GCN_MAX_IT;
    const float* hbuf = (n & 1) ? g_hB : g_hA;
    if (idx < NN*HIDN) out[H_OFF + idx] = hbuf[idx];
    else if (idx < NN*HIDN + NN*HDd) {
        int j = idx - NN*HIDN;
        out[HF_OFF + j] = g_hfull[j];
    }
}

// ---------------- launcher ----------------
extern "C" void kernel_launch(void* const* d_in, const int* in_sizes, int n_in,
                              void* d_out, int out_size)
{
    const float* x     = (const float*)d_in[0];
    const float* label = (const float*)d_in[1];
    const float* h0    = (const float*)d_in[2];
    const float* w     = (const float*)d_in[3];
    const float* dv    = (const float*)d_in[4];
    const float* l0w   = (const float*)d_in[5];
    const float* l0b   = (const float*)d_in[6];
    const float* l1w   = (const float*)d_in[7];
    const float* l1b   = (const float*)d_in[8];
    const float* l2w   = (const float*)d_in[9];
    const float* l2b   = (const float*)d_in[10];
    const float* l3w   = (const float*)d_in[11];
    const float* l3b   = (const float*)d_in[12];
    const float* l4w   = (const float*)d_in[13];
    const float* l4b   = (const float*)d_in[14];
    const float* l5w   = (const float*)d_in[15];
    const float* l5b   = (const float*)d_in[16];
    const float* W0    = (const float*)d_in[17];
    const float* B0    = (const float*)d_in[18];
    const float* W1    = (const float*)d_in[19];
    const float* B1    = (const float*)d_in[20];
    const float* W3    = (const float*)d_in[21];
    const float* B3    = (const float*)d_in[22];
    const float* v1w   = (const float*)d_in[23];
    const float* v1b   = (const float*)d_in[24];
    const float* v2w   = (const float*)d_in[25];
    const float* v2b   = (const float*)d_in[26];
    const int* gnn_step = (const int*)d_in[27];
    const int* remain   = (const int*)d_in[29];
    float* out = (float*)d_out;

    k_prep<<<NN, 128>>>(x, label, h0, w, dv, l0w, l0b, l1w, l1b, l2b, l3b, l4w, l4b, l5w, l5b);
    for (int it = 0; it < GCN_MAX_IT; it++)
        k_gcn<<<NN, HIDN>>>(w, l2w, l3w, gnn_step, it);
    k_hfull<<<NN, 128>>>(x, label, remain, gnn_step);
    k_gct<<<KK, HDd>>>(label);
    k_lg<<<NN, HDd>>>(label);
    k_wsum<<<(HDd*DMm + 255)/256, 256>>>(W0, W1);
    k_proj<<<NN, 128>>>(W0, B0, B1);
    dim3 guv(NN, NHh);
    k_uv<<<guv, 256>>>();
    k_expuv<<<100, 256>>>();
    k_vw<<<NHh*NN, 128>>>(W3);
    k_prob<<<20000, 256>>>();
    dim3 gs(8, 313);
    k_mma<<<gs, 256>>>(B3, out);
    k_qsa<<<157, 256>>>(v1w, v1b, v2w, v2b, out, out + Q_OFF);
    k_tail<<<(NN*HIDN + NN*HDd + 255)/256, 256>>>(out, gnn_step);
}

// round 12
// speedup vs baseline: 1.4464x; 1.4464x over previous
#include <cuda_runtime.h>
#include <cuda_fp16.h>
#include <math.h>

#define NN   200
#define DEGN 199
#define KK   20
#define MMg  10
#define HIDN 96
#define NHh  4
#define HDd  118
#define DMm  472
#define AJRn 30

#define S_OFF  0
#define H_OFF  18880000
#define HF_OFF 18899200
#define Q_OFF  18922800

#define GCN_MAX_IT 4

// ---------------- static device scratch ----------------
__device__ float g_stat[NN*HIDN];
__device__ float g_den1[NN], g_den2[NN];
__device__ float g_hA[NN*HIDN], g_hB[NN*HIDN];
__device__ float g_hfull[NN*HDd];
__device__ float g_gcT[KK*HDd];
__device__ float g_lg[NN*HDd];
__device__ float g_W0s[HDd*DMm], g_W1s[HDd*DMm];
__device__ float g_P1[NN*DMm], g_P2[NN*DMm];
__device__ float g_khs[NHh*HDd*NN];     // [h][d][k]
__device__ float g_vh[NHh*NN*HDd];      // [h][k][d]
__device__ float g_U[NN*NHh*NN], g_V[NN*NHh*NN];   // [(i*4+h)][k]
__device__ float g_EU[NN*NHh*NN], g_EV[NN*NHh*NN]; // exp(U - rowmax), exp(V - rowmax)
__device__ __half g_VWh[800*DMm];       // [h*200+k][c]  fp16
__device__ __half g_Pch[40000u*800u];   // 64 MB fp16

// ---------------- prep: edge sorts + static part of GCN ----------------
__global__ void k_prep(const float* __restrict__ x, const float* __restrict__ label,
                       const float* __restrict__ h0,
                       const float* __restrict__ w, const float* __restrict__ dv,
                       const float* __restrict__ l0w, const float* __restrict__ l0b,
                       const float* __restrict__ l1w, const float* __restrict__ l1b,
                       const float* __restrict__ l2b, const float* __restrict__ l3b,
                       const float* __restrict__ l4w, const float* __restrict__ l4b,
                       const float* __restrict__ l5w, const float* __restrict__ l5b)
{
    int i = blockIdx.x; int t = threadIdx.x;  // 128 threads
    int gi = i / MMg;
    __shared__ float a1[256], a2[256];
    __shared__ float red1[128], red2[128];
    float p1 = 0.f, p2 = 0.f;
    for (int e = t; e < 256; e += 128) {
        float v1 = -1e30f, v2 = -1e30f;
        if (e < DEGN) {
            int s = (e < i) ? e : e + 1;
            bool sm = (s / MMg) == gi;
            float d0 = dv[i*DEGN + e];
            float w0 = w[i*DEGN + e];
            if (sm) { v2 = d0; p2 += w0; } else { v1 = d0; p1 += w0; }
        }
        a1[e] = v1; a2[e] = v2;
    }
    red1[t] = p1; red2[t] = p2;
    __syncthreads();
    for (int off = 64; off > 0; off >>= 1) {
        if (t < off) { red1[t] += red1[t+off]; red2[t] += red2[t+off]; }
        __syncthreads();
    }
    if (t == 0) { g_den1[i] = red1[0]; g_den2[i] = red2[0]; }
    for (int ksz = 2; ksz <= 256; ksz <<= 1) {
        for (int jsz = ksz >> 1; jsz > 0; jsz >>= 1) {
            __syncthreads();
            for (int e = t; e < 256; e += 128) {
                int p = e ^ jsz;
                if (p > e) {
                    bool desc = ((e & ksz) == 0);
                    float av = a1[e], bv = a1[p];
                    if (desc ? (av < bv) : (av > bv)) { a1[e] = bv; a1[p] = av; }
                    float cv = a2[e], ev = a2[p];
                    if (desc ? (cv < ev) : (cv > ev)) { a2[e] = ev; a2[p] = cv; }
                }
            }
        }
    }
    __syncthreads();
    if (t < HIDN) {
        float acc = l0b[t] + l1b[t] + l2b[t] + l3b[t] + l4b[t] + l5b[t];
        acc += x[i*2+0]*l0w[0*HIDN+t] + x[i*2+1]*l0w[1*HIDN+t];
        for (int g = 0; g < KK; g++) acc += label[i*KK+g]*l1w[g*HIDN+t];
        for (int r = 0; r < AJRn; r++) acc += a1[r]*l4w[r*HIDN+t];
        for (int r = 0; r < MMg-1; r++) acc += a2[r]*l5w[r*HIDN+t];
        g_stat[i*HIDN+t] = acc;
        g_hA[i*HIDN+t] = h0[i*HIDN+t];
    }
}

// ---------------- one GCN iteration (early-exit past gnn_step) ----------------
__global__ void k_gcn(const float* __restrict__ w,
                      const float* __restrict__ l2w, const float* __restrict__ l3w,
                      const int* __restrict__ gnn_step, int iter)
{
    if (!(iter < *gnn_step)) return;
    int i = blockIdx.x, c = threadIdx.x;  // 96 threads
    const float* hin  = (iter & 1) ? g_hB : g_hA;
    float*       hout = (iter & 1) ? g_hA : g_hB;
    int gi = i / MMg;
    float acc1 = 0.f, acc2 = 0.f;
    __shared__ float sn1[HIDN], sn2[HIDN];
    for (int s = 0; s < NN; s++) {
        if (s == i) continue;
        int j = s - (s > i);
        float wv = w[i*DEGN + j];
        float hv = hin[s*HIDN + c];
        if (s / MMg == gi) acc2 += wv*hv; else acc1 += wv*hv;
    }
    sn1[c] = acc1 / g_den1[i];
    sn2[c] = acc2 / g_den2[i];
    __syncthreads();
    float o = g_stat[i*HIDN + c];
    for (int r = 0; r < HIDN; r++)
        o += sn1[r]*l2w[r*HIDN+c] + sn2[r]*l3w[r*HIDN+c];
    hout[i*HIDN + c] = fmaxf(o, 0.f);
}

// ---------------- h_full = [h + pe, x, label]  (parity-select h buffer) ----------------
__global__ void k_hfull(const float* __restrict__ x, const float* __restrict__ label,
                        const int* __restrict__ remain, const int* __restrict__ gnn_step)
{
    int i = blockIdx.x, t = threadIdx.x;
    if (t >= HDd) return;
    int n = *gnn_step; if (n > GCN_MAX_IT) n = GCN_MAX_IT;
    const float* hbuf = (n & 1) ? g_hB : g_hA;
    float v;
    if (t < HIDN) {
        int p = *remain;
        int k2 = t & ~1;
        double div = exp(-(double)k2 * log(10000.0) / (double)HIDN);
        double ang = (double)p * div;
        v = hbuf[i*HIDN + t] + (float)((t & 1) ? cos(ang) : sin(ang));
    } else if (t < HIDN + 2) v = x[i*2 + (t - HIDN)];
    else v = label[i*KK + (t - HIDN - 2)];
    g_hfull[i*HDd + t] = v;
}

__global__ void k_gct(const float* __restrict__ label)
{
    int g = blockIdx.x, dd = threadIdx.x;
    float acc = 0.f;
    for (int i = 0; i < NN; i++) acc += label[i*KK + g] * g_hfull[i*HDd + dd];
    g_gcT[g*HDd + dd] = acc * 0.1f;
}

__global__ void k_lg(const float* __restrict__ label)
{
    int i = blockIdx.x, dd = threadIdx.x;
    float acc = 0.f;
    for (int g = 0; g < KK; g++) acc += label[i*KK + g] * g_gcT[g*HDd + dd];
    g_lg[i*HDd + dd] = acc;
}

__global__ void k_wsum(const float* __restrict__ W0, const float* __restrict__ W1)
{
    int idx = blockIdx.x * blockDim.x + threadIdx.x;
    if (idx >= HDd*DMm) return;
    int d = idx / DMm, c = idx % DMm;
    g_W0s[idx] = W0[d*DMm+c] + W0[(118+d)*DMm+c] + W0[(236+d)*DMm+c] + W0[(354+d)*DMm+c];
    g_W1s[idx] = W1[d*DMm+c] + W1[(118+d)*DMm+c] + W1[(236+d)*DMm+c] + W1[(354+d)*DMm+c];
}

// ---------------- per-node projections ----------------
__global__ void k_proj(const float* __restrict__ W0, const float* __restrict__ B0,
                       const float* __restrict__ B1)
{
    int i = blockIdx.x, t = threadIdx.x;  // 128 threads
    __shared__ float hf[HDd], lgs[HDd];
    if (t < HDd) { hf[t] = g_hfull[i*HDd + t]; lgs[t] = g_lg[i*HDd + t]; }
    __syncthreads();
    const float scale = 1.0f / sqrtf((float)HDd);
    for (int c = t; c < DMm; c += 128) {
        float p1 = B0[c], p2 = 0.f, kf = B0[c], vf = B1[c];
        for (int d = 0; d < HDd; d++) {
            float hv = hf[d], lv = lgs[d];
            p1 += hv * W0[d*DMm + c]       + lv * W0[(236+d)*DMm + c];
            p2 += hv * W0[(118+d)*DMm + c] + lv * W0[(354+d)*DMm + c];
            kf += hv * g_W0s[d*DMm + c];
            vf += hv * g_W1s[d*DMm + c];
        }
        g_P1[i*DMm + c] = p1;
        g_P2[i*DMm + c] = p2;
        int h = c / HDd, dd = c % HDd;
        g_khs[(h*HDd + dd)*NN + i] = kf * scale;
        g_vh[(h*NN + i)*HDd + dd] = vf;
    }
}

// ---------------- U/V score components ----------------
__global__ void k_uv()
{
    int i = blockIdx.x, h = blockIdx.y, t = threadIdx.x;  // 256 threads
    __shared__ float s1[HDd], s2[HDd];
    if (t < HDd) {
        s1[t] = g_P1[i*DMm + h*HDd + t];
        s2[t] = g_P2[i*DMm + h*HDd + t];
    }
    __syncthreads();
    if (t < NN) {
        float u = 0.f, v = 0.f;
        for (int d = 0; d < HDd; d++) {
            float kv = g_khs[(h*HDd + d)*NN + t];
            u += s1[d] * kv;
            v += s2[d] * kv;
        }
        g_U[(i*NHh + h)*NN + t] = u;
        g_V[(i*NHh + h)*NN + t] = v;
    }
}

// ---------------- EU/EV: rowwise exp(x - rowmax) ----------------
__global__ void k_expuv()
{
    int row = blockIdx.x * 8 + (threadIdx.x >> 5);   // 0..799
    int lane = threadIdx.x & 31;
    const float* Ur = g_U + row * NN;
    const float* Vr = g_V + row * NN;
    float u[7], v[7];
    float mu = -1e30f, mv = -1e30f;
    #pragma unroll
    for (int r = 0; r < 7; r++) {
        int k = lane + 32*r;
        if (k < NN) {
            u[r] = Ur[k]; v[r] = Vr[k];
            mu = fmaxf(mu, u[r]); mv = fmaxf(mv, v[r]);
        } else { u[r] = -1e30f; v[r] = -1e30f; }
    }
    #pragma unroll
    for (int o = 16; o > 0; o >>= 1) {
        mu = fmaxf(mu, __shfl_xor_sync(0xffffffffu, mu, o));
        mv = fmaxf(mv, __shfl_xor_sync(0xffffffffu, mv, o));
    }
    #pragma unroll
    for (int r = 0; r < 7; r++) {
        int k = lane + 32*r;
        if (k < NN) {
            g_EU[row * NN + k] = __expf(u[r] - mu);
            g_EV[row * NN + k] = __expf(v[r] - mv);
        }
    }
}

// ---------------- pair-softmax: 2 pairs (same i) per block ----------------
__global__ __launch_bounds__(256) void k_prob()
{
    int b0 = blockIdx.x * 2;
    int i = b0 / NN, j0 = b0 % NN;     // j0 even -> j0+1 < 200
    int w = threadIdx.x >> 5;
    int lane = threadIdx.x & 31;
    int h = w & 3, side = w >> 2;
    __shared__ float s[2][800];

    // side0: p = EU_i * EV_j ; side1: p = EU_j * EV_i
    const float* Ei = side ? (g_EV + (i*NHh + h)*NN) : (g_EU + (i*NHh + h)*NN);
    float a[7];
    #pragma unroll
    for (int r = 0; r < 7; r++) {
        int k = lane + 32*r;
        a[r] = (k < NN) ? Ei[k] : 0.f;
    }

    #pragma unroll
    for (int jj = 0; jj < 2; jj++) {
        int j = j0 + jj;
        const float* Ej = side ? (g_EU + (j*NHh + h)*NN) : (g_EV + (j*NHh + h)*NN);
        float p[7];
        float sum = 0.f;
        #pragma unroll
        for (int r = 0; r < 7; r++) {
            int k = lane + 32*r;
            if (k < NN) { p[r] = a[r] * Ej[k]; sum += p[r]; }
            else p[r] = 0.f;
        }
        #pragma unroll
        for (int o = 16; o > 0; o >>= 1)
            sum += __shfl_xor_sync(0xffffffffu, sum, o);
        float inv = 1.f / sum;

        if (side == 1) {
            #pragma unroll
            for (int r = 0; r < 7; r++) {
                int k = lane + 32*r;
                if (k < NN) s[jj][h*200 + k] = p[r] * inv;
            }
        }
        __syncthreads();
        if (side == 0) {
            #pragma unroll
            for (int r = 0; r < 7; r++) {
                int k = lane + 32*r;
                if (k < NN) s[jj][h*200 + k] = p[r] * inv + s[jj][h*200 + k];
            }
        }
        __syncthreads();
    }
    #pragma unroll
    for (int jj = 0; jj < 2; jj++) {
        __half2* dst = (__half2*)(g_Pch + (size_t)(b0 + jj) * 800);
        for (int t2 = threadIdx.x; t2 < 400; t2 += 256)
            dst[t2] = __floats2half2_rn(s[jj][2*t2], s[jj][2*t2 + 1]);
    }
}

// ---------------- VW (fp16) ----------------
__global__ void k_vw(const float* __restrict__ W3)
{
    int row = blockIdx.x, t = threadIdx.x;  // 128 threads
    int h = row / NN, k = row % NN;
    __shared__ float vr[HDd];
    if (t < HDd) vr[t] = g_vh[(h*NN + k)*HDd + t];
    __syncthreads();
    for (int c = t; c < DMm; c += 128) {
        float acc = 0.f;
        for (int d = 0; d < HDd; d++) acc += vr[d] * W3[(h*HDd + d)*DMm + c];
        g_VWh[row*DMm + c] = __float2half_rn(acc);
    }
}

// ---------------- fp16 MMA GEMM: S = Pc(40000x800) @ VW(800x472) + 2*b3 ----------------
#define BMt 128
#define BNt 64
#define BKt 32
#define A_STRIDE 40
#define B_STRIDE 72
#define A_BYTES  (BMt * A_STRIDE * 2)
#define B_BYTES  (BKt * B_STRIDE * 2)
#define STG_BYTES (A_BYTES + B_BYTES)
#define KT 25

__device__ __forceinline__ void cp_async16(unsigned dst, const void* src, int src_bytes) {
    asm volatile("cp.async.cg.shared.global [%0], [%1], 16, %2;\n"
                 :: "r"(dst), "l"(src), "r"(src_bytes));
}
__device__ __forceinline__ void cp_commit() {
    asm volatile("cp.async.commit_group;\n");
}
__device__ __forceinline__ void cp_wait1() {
    asm volatile("cp.async.wait_group 1;\n");
}
__device__ __forceinline__ void ldmA4(unsigned* r, unsigned addr) {
    asm volatile("ldmatrix.sync.aligned.m8n8.x4.shared.b16 {%0,%1,%2,%3}, [%4];"
                 : "=r"(r[0]), "=r"(r[1]), "=r"(r[2]), "=r"(r[3]) : "r"(addr));
}
__device__ __forceinline__ void ldmBT4(unsigned* r, unsigned addr) {
    asm volatile("ldmatrix.sync.aligned.m8n8.x4.trans.shared.b16 {%0,%1,%2,%3}, [%4];"
                 : "=r"(r[0]), "=r"(r[1]), "=r"(r[2]), "=r"(r[3]) : "r"(addr));
}
__device__ __forceinline__ void mma_f16(float* c, const unsigned* a, const unsigned* b) {
    asm volatile("mma.sync.aligned.m16n8k16.row.col.f32.f16.f16.f32 "
                 "{%0,%1,%2,%3},{%4,%5,%6,%7},{%8,%9},{%0,%1,%2,%3};"
                 : "+f"(c[0]), "+f"(c[1]), "+f"(c[2]), "+f"(c[3])
                 : "r"(a[0]), "r"(a[1]), "r"(a[2]), "r"(a[3]), "r"(b[0]), "r"(b[1]));
}

__device__ __forceinline__ void load_stage(unsigned sbase, int stage, int k0,
                                           int bm, int bn, int t)
{
    unsigned sa = sbase + stage * STG_BYTES;
    unsigned sb = sa + A_BYTES;
    #pragma unroll
    for (int p = 0; p < 2; p++) {
        int li = t + p * 256;
        int row = li >> 2, ch = li & 3;
        int grow = bm + row;
        bool ok = (grow < 40000);
        const __half* src = g_Pch + (size_t)(ok ? grow : 0) * 800 + k0 + ch * 8;
        cp_async16(sa + (unsigned)(row * A_STRIDE + ch * 8) * 2, src, ok ? 16 : 0);
    }
    {
        int k = t >> 3, ch = t & 7;
        int col = bn + ch * 8;
        int rem = DMm - col;
        int sz = (rem >= 8) ? 16 : ((rem > 0) ? rem * 2 : 0);
        const __half* src = g_VWh + (size_t)(k0 + k) * DMm + ((col < DMm) ? col : 0);
        cp_async16(sb + (unsigned)(k * B_STRIDE + ch * 8) * 2, src, sz);
    }
}

__global__ __launch_bounds__(256) void k_mma(const float* __restrict__ B3,
                                             float* __restrict__ out)
{
    __shared__ __align__(16) unsigned char smem[3 * STG_BYTES];
    unsigned sbase = (unsigned)__cvta_generic_to_shared(smem);

    int t = threadIdx.x;
    int w = t >> 5, lane = t & 31;
    int wm = (w & 3) * 32;
    int wn = (w >> 2) * 32;
    int bm = blockIdx.y * BMt, bn = blockIdx.x * BNt;

    float acc[2][4][4];
    #pragma unroll
    for (int mm = 0; mm < 2; mm++)
        #pragma unroll
        for (int nn = 0; nn < 4; nn++)
            #pragma unroll
            for (int q = 0; q < 4; q++) acc[mm][nn][q] = 0.f;

    int arow = wm + (lane & 15);
    int acb  = (lane >> 4) * 8;
    int bkl  = (lane & 7) + (lane & 8);
    int bnl  = wn + ((lane >> 4) * 8);

    load_stage(sbase, 0, 0, bm, bn, t);  cp_commit();
    load_stage(sbase, 1, 32, bm, bn, t); cp_commit();

    for (int kt = 0; kt < KT; kt++) {
        cp_wait1();
        __syncthreads();
        // prefetch kt+2 into stage last read at iter kt-1 (protected by trailing sync)
        if (kt + 2 < KT) load_stage(sbase, (kt + 2) % 3, (kt + 2) * BKt, bm, bn, t);
        cp_commit();
        unsigned sa = sbase + (kt % 3) * STG_BYTES;
        unsigned sb = sa + A_BYTES;
        #pragma unroll
        for (int ks = 0; ks < 2; ks++) {
            unsigned af[2][4], bf[2][4];
            ldmA4(af[0], sa + (unsigned)((arow)      * A_STRIDE + ks * 16 + acb) * 2);
            ldmA4(af[1], sa + (unsigned)((arow + 16) * A_STRIDE + ks * 16 + acb) * 2);
            ldmBT4(bf[0], sb + (unsigned)((ks * 16 + bkl) * B_STRIDE + bnl) * 2);
            ldmBT4(bf[1], sb + (unsigned)((ks * 16 + bkl) * B_STRIDE + bnl + 16) * 2);
            #pragma unroll
            for (int mm = 0; mm < 2; mm++) {
                mma_f16(acc[mm][0], af[mm], bf[0] + 0);
                mma_f16(acc[mm][1], af[mm], bf[0] + 2);
                mma_f16(acc[mm][2], af[mm], bf[1] + 0);
                mma_f16(acc[mm][3], af[mm], bf[1] + 2);
            }
        }
        __syncthreads();
    }

    int r0 = bm + wm + (lane >> 2);
    int c0 = bn + wn + (lane & 3) * 2;
    #pragma unroll
    for (int mm = 0; mm < 2; mm++) {
        int rbase = r0 + mm * 16;
        #pragma unroll
        for (int nn = 0; nn < 4; nn++) {
            int c = c0 + nn * 8;
            if (c < DMm) {
                float b3a = 2.f * B3[c], b3b = 2.f * B3[c + 1];
                if (rbase < 40000) {
                    float2 v = make_float2(acc[mm][nn][0] + b3a, acc[mm][nn][1] + b3b);
                    *(float2*)&out[(size_t)rbase * DMm + c] = v;
                }
                if (rbase + 8 < 40000) {
                    float2 v = make_float2(acc[mm][nn][2] + b3a, acc[mm][nn][3] + b3b);
                    *(float2*)&out[(size_t)(rbase + 8) * DMm + c] = v;
                }
            }
        }
    }
}

// ---------------- Q_sa: smem-tiled GEMM, 256 rows/block, 4x12 per thread ----------------
#define QROWS 256
#define QKT   32
__global__ __launch_bounds__(256) void k_qsa(const float* __restrict__ v1w,
                                             const float* __restrict__ v1b,
                                             const float* __restrict__ v2w,
                                             const float* __restrict__ v2b,
                                             const float* __restrict__ S,
                                             float* __restrict__ qout)
{
    __shared__ float sS[QKT][QROWS + 1];
    __shared__ float sW[QKT][48];

    int tid = threadIdx.x;
    int ty = tid >> 2;
    int tx = tid & 3;
    int base = blockIdx.x * QROWS;

    float acc[4][12];
    #pragma unroll
    for (int r = 0; r < 4; r++)
        #pragma unroll
        for (int c = 0; c < 12; c++) acc[r][c] = 0.f;

    for (int k0 = 0; k0 < DMm; k0 += QKT) {
        int TK = DMm - k0; if (TK > QKT) TK = QKT;
        #pragma unroll
        for (int it = 0; it < 8; it++) {
            int idx = tid + it * 256;
            int r = idx >> 3;
            int c4 = idx & 7;
            int k = c4 * 4;
            if (k < TK) {
                int grow = base + r;
                const float* src = S + (size_t)(grow < 40000 ? grow : 0) * DMm + k0 + k;
                float4 v = *(const float4*)src;
                sS[k + 0][r] = v.x; sS[k + 1][r] = v.y;
                sS[k + 2][r] = v.z; sS[k + 3][r] = v.w;
            }
        }
        #pragma unroll
        for (int it = 0; it < 6; it++) {
            int idx = tid + it * 256;
            int k = idx / 48, c = idx - k * 48;
            if (k < TK)
                sW[k][c] = v1w[(k0 + k) * 48 + c];
        }
        __syncthreads();
        for (int k = 0; k < TK; k++) {
            float a0 = sS[k][ty * 4 + 0];
            float a1 = sS[k][ty * 4 + 1];
            float a2 = sS[k][ty * 4 + 2];
            float a3 = sS[k][ty * 4 + 3];
            #pragma unroll
            for (int c = 0; c < 12; c++) {
                float wv = sW[k][tx * 12 + c];
                acc[0][c] += a0 * wv;
                acc[1][c] += a1 * wv;
                acc[2][c] += a2 * wv;
                acc[3][c] += a3 * wv;
            }
        }
        __syncthreads();
    }

    float b1[12], w2[12];
    #pragma unroll
    for (int c = 0; c < 12; c++) {
        b1[c] = v1b[tx * 12 + c];
        w2[c] = v2w[tx * 12 + c];
    }
    float vb2 = v2b[0];
    #pragma unroll
    for (int r = 0; r < 4; r++) {
        float part = 0.f;
        #pragma unroll
        for (int c = 0; c < 12; c++)
            part += fmaxf(acc[r][c] + b1[c], 0.f) * w2[c];
        part += __shfl_xor_sync(0xffffffffu, part, 1);
        part += __shfl_xor_sync(0xffffffffu, part, 2);
        int row = base + ty * 4 + r;
        if (tx == 0 && row < 40000) qout[row] = part + vb2;
    }
}

// ---------------- tail: copy h, h_full into output ----------------
__global__ void k_tail(float* __restrict__ out, const int* __restrict__ gnn_step)
{
    int idx = blockIdx.x * blockDim.x + threadIdx.x;
    int n = *gnn_step; if (n > GCN_MAX_IT) n = GCN_MAX_IT;
    const float* hbuf = (n & 1) ? g_hB : g_hA;
    if (idx < NN*HIDN) out[H_OFF + idx] = hbuf[idx];
    else if (idx < NN*HIDN + NN*HDd) {
        int j = idx - NN*HIDN;
        out[HF_OFF + j] = g_hfull[j];
    }
}

// ---------------- launcher ----------------
extern "C" void kernel_launch(void* const* d_in, const int* in_sizes, int n_in,
                              void* d_out, int out_size)
{
    const float* x     = (const float*)d_in[0];
    const float* label = (const float*)d_in[1];
    const float* h0    = (const float*)d_in[2];
    const float* w     = (const float*)d_in[3];
    const float* dv    = (const float*)d_in[4];
    const float* l0w   = (const float*)d_in[5];
    const float* l0b   = (const float*)d_in[6];
    const float* l1w   = (const float*)d_in[7];
    const float* l1b   = (const float*)d_in[8];
    const float* l2w   = (const float*)d_in[9];
    const float* l2b   = (const float*)d_in[10];
    const float* l3w   = (const float*)d_in[11];
    const float* l3b   = (const float*)d_in[12];
    const float* l4w   = (const float*)d_in[13];
    const float* l4b   = (const float*)d_in[14];
    const float* l5w   = (const float*)d_in[15];
    const float* l5b   = (const float*)d_in[16];
    const float* W0    = (const float*)d_in[17];
    const float* B0    = (const float*)d_in[18];
    const float* W1    = (const float*)d_in[19];
    const float* B1    = (const float*)d_in[20];
    const float* W3    = (const float*)d_in[21];
    const float* B3    = (const float*)d_in[22];
    const float* v1w   = (const float*)d_in[23];
    const float* v1b   = (const float*)d_in[24];
    const float* v2w   = (const float*)d_in[25];
    const float* v2b   = (const float*)d_in[26];
    const int* gnn_step = (const int*)d_in[27];
    const int* remain   = (const int*)d_in[29];
    float* out = (float*)d_out;

    k_prep<<<NN, 128>>>(x, label, h0, w, dv, l0w, l0b, l1w, l1b, l2b, l3b, l4w, l4b, l5w, l5b);
    for (int it = 0; it < GCN_MAX_IT; it++)
        k_gcn<<<NN, HIDN>>>(w, l2w, l3w, gnn_step, it);
    k_hfull<<<NN, 128>>>(x, label, remain, gnn_step);
    k_gct<<<KK, HDd>>>(label);
    k_lg<<<NN, HDd>>>(label);
    k_wsum<<<(HDd*DMm + 255)/256, 256>>>(W0, W1);
    k_proj<<<NN, 128>>>(W0, B0, B1);
    dim3 guv(NN, NHh);
    k_uv<<<guv, 256>>>();
    k_expuv<<<100, 256>>>();
    k_vw<<<NHh*NN, 128>>>(W3);
    k_prob<<<20000, 256>>>();
    dim3 gs(8, 313);
    k_mma<<<gs, 256>>>(B3, out);
    k_qsa<<<157, 256>>>(v1w, v1b, v2w, v2b, out, out + Q_OFF);
    k_tail<<<(NN*HIDN + NN*HDd + 255)/256, 256>>>(out, gnn_step);
}

// round 17
// speedup vs baseline: 1.6822x; 1.1630x over previous
#include <cuda_runtime.h>
#include <cuda_fp16.h>
#include <math.h>

#define NN   200
#define DEGN 199
#define KK   20
#define MMg  10
#define HIDN 96
#define NHh  4
#define HDd  118
#define DMm  472
#define AJRn 30

#define S_OFF  0
#define H_OFF  18880000
#define HF_OFF 18899200
#define Q_OFF  18922800

#define GCN_MAX_IT 4
#define MP    20100          // packed upper-triangular pairs (i<=j)
#define MTILE 158            // ceil(MP/128)

// ---------------- static device scratch ----------------
__device__ float g_stat[NN*HIDN];
__device__ float g_den1[NN], g_den2[NN];
__device__ float g_hA[NN*HIDN], g_hB[NN*HIDN];
__device__ float g_hfull[NN*HDd];
__device__ float g_gcT[KK*HDd];
__device__ float g_lg[NN*HDd];
__device__ float g_W0s[HDd*DMm], g_W1s[HDd*DMm];
__device__ float g_P1[NN*DMm], g_P2[NN*DMm];
__device__ float g_khs[NHh*HDd*NN];     // [h][d][k]
__device__ float g_vh[NHh*NN*HDd];      // [h][k][d]
__device__ float g_U[NN*NHh*NN], g_V[NN*NHh*NN];   // [(i*4+h)][k]
__device__ float g_EU[NN*NHh*NN], g_EV[NN*NHh*NN]; // exp(U - rowmax), exp(V - rowmax)
__device__ __half g_VWh[800*DMm];       // [h*200+k][c]  fp16
__device__ __half g_Pch[(size_t)MP*800u];  // packed pair probs, fp16
__device__ float g_Sp[(size_t)MP*DMm];     // packed S rows
__device__ float g_Qp[MP];                 // packed Q_sa
__device__ int2  g_pairs[MP];              // pid -> (i,j)

// ---------------- prep: edge sorts + static part of GCN ----------------
__global__ void k_prep(const float* __restrict__ x, const float* __restrict__ label,
                       const float* __restrict__ h0,
                       const float* __restrict__ w, const float* __restrict__ dv,
                       const float* __restrict__ l0w, const float* __restrict__ l0b,
                       const float* __restrict__ l1w, const float* __restrict__ l1b,
                       const float* __restrict__ l2b, const float* __restrict__ l3b,
                       const float* __restrict__ l4w, const float* __restrict__ l4b,
                       const float* __restrict__ l5w, const float* __restrict__ l5b)
{
    int i = blockIdx.x; int t = threadIdx.x;  // 128 threads
    int gi = i / MMg;
    __shared__ float a1[256], a2[256];
    __shared__ float red1[128], red2[128];
    float p1 = 0.f, p2 = 0.f;
    for (int e = t; e < 256; e += 128) {
        float v1 = -1e30f, v2 = -1e30f;
        if (e < DEGN) {
            int s = (e < i) ? e : e + 1;
            bool sm = (s / MMg) == gi;
            float d0 = dv[i*DEGN + e];
            float w0 = w[i*DEGN + e];
            if (sm) { v2 = d0; p2 += w0; } else { v1 = d0; p1 += w0; }
        }
        a1[e] = v1; a2[e] = v2;
    }
    red1[t] = p1; red2[t] = p2;
    __syncthreads();
    for (int off = 64; off > 0; off >>= 1) {
        if (t < off) { red1[t] += red1[t+off]; red2[t] += red2[t+off]; }
        __syncthreads();
    }
    if (t == 0) { g_den1[i] = red1[0]; g_den2[i] = red2[0]; }
    for (int ksz = 2; ksz <= 256; ksz <<= 1) {
        for (int jsz = ksz >> 1; jsz > 0; jsz >>= 1) {
            __syncthreads();
            for (int e = t; e < 256; e += 128) {
                int p = e ^ jsz;
                if (p > e) {
                    bool desc = ((e & ksz) == 0);
                    float av = a1[e], bv = a1[p];
                    if (desc ? (av < bv) : (av > bv)) { a1[e] = bv; a1[p] = av; }
                    float cv = a2[e], ev = a2[p];
                    if (desc ? (cv < ev) : (cv > ev)) { a2[e] = ev; a2[p] = cv; }
                }
            }
        }
    }
    __syncthreads();
    if (t < HIDN) {
        float acc = l0b[t] + l1b[t] + l2b[t] + l3b[t] + l4b[t] + l5b[t];
        acc += x[i*2+0]*l0w[0*HIDN+t] + x[i*2+1]*l0w[1*HIDN+t];
        for (int g = 0; g < KK; g++) acc += label[i*KK+g]*l1w[g*HIDN+t];
        for (int r = 0; r < AJRn; r++) acc += a1[r]*l4w[r*HIDN+t];
        for (int r = 0; r < MMg-1; r++) acc += a2[r]*l5w[r*HIDN+t];
        g_stat[i*HIDN+t] = acc;
        g_hA[i*HIDN+t] = h0[i*HIDN+t];
    }
}

// ---------------- pid -> (i,j) LUT ----------------
__global__ void k_pairs()
{
    int p = blockIdx.x * 256 + threadIdx.x;
    if (p >= MP) return;
    double disc = 160801.0 - 8.0 * (double)p;   // (2N+1)^2 - 8p
    int i = (int)((401.0 - sqrt(disc)) * 0.5);
    if (i < 0) i = 0; if (i > NN-1) i = NN-1;
    while (i > 0 && i*NN - i*(i-1)/2 > p) i--;
    while ((i+1)*NN - (i+1)*i/2 <= p) i++;
    int j = i + (p - (i*NN - i*(i-1)/2));
    g_pairs[p] = make_int2(i, j);
}

// ---------------- one GCN iteration (early-exit past gnn_step) ----------------
__global__ void k_gcn(const float* __restrict__ w,
                      const float* __restrict__ l2w, const float* __restrict__ l3w,
                      const int* __restrict__ gnn_step, int iter)
{
    if (!(iter < *gnn_step)) return;
    int i = blockIdx.x, c = threadIdx.x;  // 96 threads
    const float* hin  = (iter & 1) ? g_hB : g_hA;
    float*       hout = (iter & 1) ? g_hA : g_hB;
    int gi = i / MMg;
    float acc1 = 0.f, acc2 = 0.f;
    __shared__ float sn1[HIDN], sn2[HIDN];
    for (int s = 0; s < NN; s++) {
        if (s == i) continue;
        int j = s - (s > i);
        float wv = w[i*DEGN + j];
        float hv = hin[s*HIDN + c];
        if (s / MMg == gi) acc2 += wv*hv; else acc1 += wv*hv;
    }
    sn1[c] = acc1 / g_den1[i];
    sn2[c] = acc2 / g_den2[i];
    __syncthreads();
    float o = g_stat[i*HIDN + c];
    for (int r = 0; r < HIDN; r++)
        o += sn1[r]*l2w[r*HIDN+c] + sn2[r]*l3w[r*HIDN+c];
    hout[i*HIDN + c] = fmaxf(o, 0.f);
}

// ---------------- h_full = [h + pe, x, label]  (parity-select h buffer) ----------------
__global__ void k_hfull(const float* __restrict__ x, const float* __restrict__ label,
                        const int* __restrict__ remain, const int* __restrict__ gnn_step)
{
    int i = blockIdx.x, t = threadIdx.x;
    if (t >= HDd) return;
    int n = *gnn_step; if (n > GCN_MAX_IT) n = GCN_MAX_IT;
    const float* hbuf = (n & 1) ? g_hB : g_hA;
    float v;
    if (t < HIDN) {
        int p = *remain;
        int k2 = t & ~1;
        double div = exp(-(double)k2 * log(10000.0) / (double)HIDN);
        double ang = (double)p * div;
        v = hbuf[i*HIDN + t] + (float)((t & 1) ? cos(ang) : sin(ang));
    } else if (t < HIDN + 2) v = x[i*2 + (t - HIDN)];
    else v = label[i*KK + (t - HIDN - 2)];
    g_hfull[i*HDd + t] = v;
}

__global__ void k_gct(const float* __restrict__ label)
{
    int g = blockIdx.x, dd = threadIdx.x;
    float acc = 0.f;
    for (int i = 0; i < NN; i++) acc += label[i*KK + g] * g_hfull[i*HDd + dd];
    g_gcT[g*HDd + dd] = acc * 0.1f;
}

__global__ void k_lg(const float* __restrict__ label)
{
    int i = blockIdx.x, dd = threadIdx.x;
    float acc = 0.f;
    for (int g = 0; g < KK; g++) acc += label[i*KK + g] * g_gcT[g*HDd + dd];
    g_lg[i*HDd + dd] = acc;
}

__global__ void k_wsum(const float* __restrict__ W0, const float* __restrict__ W1)
{
    int idx = blockIdx.x * blockDim.x + threadIdx.x;
    if (idx >= HDd*DMm) return;
    int d = idx / DMm, c = idx % DMm;
    g_W0s[idx] = W0[d*DMm+c] + W0[(118+d)*DMm+c] + W0[(236+d)*DMm+c] + W0[(354+d)*DMm+c];
    g_W1s[idx] = W1[d*DMm+c] + W1[(118+d)*DMm+c] + W1[(236+d)*DMm+c] + W1[(354+d)*DMm+c];
}

// ---------------- per-node projections ----------------
__global__ void k_proj(const float* __restrict__ W0, const float* __restrict__ B0,
                       const float* __restrict__ B1)
{
    int i = blockIdx.x, t = threadIdx.x;  // 128 threads
    __shared__ float hf[HDd], lgs[HDd];
    if (t < HDd) { hf[t] = g_hfull[i*HDd + t]; lgs[t] = g_lg[i*HDd + t]; }
    __syncthreads();
    const float scale = 1.0f / sqrtf((float)HDd);
    for (int c = t; c < DMm; c += 128) {
        float p1 = B0[c], p2 = 0.f, kf = B0[c], vf = B1[c];
        for (int d = 0; d < HDd; d++) {
            float hv = hf[d], lv = lgs[d];
            p1 += hv * W0[d*DMm + c]       + lv * W0[(236+d)*DMm + c];
            p2 += hv * W0[(118+d)*DMm + c] + lv * W0[(354+d)*DMm + c];
            kf += hv * g_W0s[d*DMm + c];
            vf += hv * g_W1s[d*DMm + c];
        }
        g_P1[i*DMm + c] = p1;
        g_P2[i*DMm + c] = p2;
        int h = c / HDd, dd = c % HDd;
        g_khs[(h*HDd + dd)*NN + i] = kf * scale;
        g_vh[(h*NN + i)*HDd + dd] = vf;
    }
}

// ---------------- U/V score components ----------------
__global__ void k_uv()
{
    int i = blockIdx.x, h = blockIdx.y, t = threadIdx.x;  // 256 threads
    __shared__ float s1[HDd], s2[HDd];
    if (t < HDd) {
        s1[t] = g_P1[i*DMm + h*HDd + t];
        s2[t] = g_P2[i*DMm + h*HDd + t];
    }
    __syncthreads();
    if (t < NN) {
        float u = 0.f, v = 0.f;
        for (int d = 0; d < HDd; d++) {
            float kv = g_khs[(h*HDd + d)*NN + t];
            u += s1[d] * kv;
            v += s2[d] * kv;
        }
        g_U[(i*NHh + h)*NN + t] = u;
        g_V[(i*NHh + h)*NN + t] = v;
    }
}

// ---------------- EU/EV: rowwise exp(x - rowmax) ----------------
__global__ void k_expuv()
{
    int row = blockIdx.x * 8 + (threadIdx.x >> 5);   // 0..799
    int lane = threadIdx.x & 31;
    const float* Ur = g_U + row * NN;
    const float* Vr = g_V + row * NN;
    float u[7], v[7];
    float mu = -1e30f, mv = -1e30f;
    #pragma unroll
    for (int r = 0; r < 7; r++) {
        int k = lane + 32*r;
        if (k < NN) {
            u[r] = Ur[k]; v[r] = Vr[k];
            mu = fmaxf(mu, u[r]); mv = fmaxf(mv, v[r]);
        } else { u[r] = -1e30f; v[r] = -1e30f; }
    }
    #pragma unroll
    for (int o = 16; o > 0; o >>= 1) {
        mu = fmaxf(mu, __shfl_xor_sync(0xffffffffu, mu, o));
        mv = fmaxf(mv, __shfl_xor_sync(0xffffffffu, mv, o));
    }
    #pragma unroll
    for (int r = 0; r < 7; r++) {
        int k = lane + 32*r;
        if (k < NN) {
            g_EU[row * NN + k] = __expf(u[r] - mu);
            g_EV[row * NN + k] = __expf(v[r] - mv);
        }
    }
}

// ---------------- pair-softmax on packed upper-triangular pairs ----------------
__global__ __launch_bounds__(256) void k_prob()
{
    int pid = blockIdx.x;
    int2 ij = g_pairs[pid];
    int i = ij.x, j = ij.y;
    int w = threadIdx.x >> 5;
    int lane = threadIdx.x & 31;
    int h = w & 3, side = w >> 2;
    __shared__ float s[800];

    // side0: p = EU_i * EV_j ; side1: p = EU_j * EV_i
    const float* EA = side ? (g_EU + (j*NHh + h)*NN) : (g_EU + (i*NHh + h)*NN);
    const float* EB = side ? (g_EV + (i*NHh + h)*NN) : (g_EV + (j*NHh + h)*NN);

    float p[7];
    float sum = 0.f;
    #pragma unroll
    for (int r = 0; r < 7; r++) {
        int k = lane + 32*r;
        if (k < NN) { p[r] = EA[k] * EB[k]; sum += p[r]; }
        else p[r] = 0.f;
    }
    #pragma unroll
    for (int o = 16; o > 0; o >>= 1)
        sum += __shfl_xor_sync(0xffffffffu, sum, o);
    float inv = 1.f / sum;

    if (side == 1) {
        #pragma unroll
        for (int r = 0; r < 7; r++) {
            int k = lane + 32*r;
            if (k < NN) s[h*200 + k] = p[r] * inv;
        }
    }
    __syncthreads();
    if (side == 0) {
        #pragma unroll
        for (int r = 0; r < 7; r++) {
            int k = lane + 32*r;
            if (k < NN) s[h*200 + k] = p[r] * inv + s[h*200 + k];
        }
    }
    __syncthreads();
    __half2* dst = (__half2*)(g_Pch + (size_t)pid * 800);
    for (int t2 = threadIdx.x; t2 < 400; t2 += 256)
        dst[t2] = __floats2half2_rn(s[2*t2], s[2*t2 + 1]);
}

// ---------------- VW (fp16) ----------------
__global__ void k_vw(const float* __restrict__ W3)
{
    int row = blockIdx.x, t = threadIdx.x;  // 128 threads
    int h = row / NN, k = row % NN;
    __shared__ float vr[HDd];
    if (t < HDd) vr[t] = g_vh[(h*NN + k)*HDd + t];
    __syncthreads();
    for (int c = t; c < DMm; c += 128) {
        float acc = 0.f;
        for (int d = 0; d < HDd; d++) acc += vr[d] * W3[(h*HDd + d)*DMm + c];
        g_VWh[row*DMm + c] = __float2half_rn(acc);
    }
}

// ---------------- fp16 MMA GEMM: Sp = Pc(MP x 800) @ VW(800x472) + 2*b3 ----------------
#define BMt 128
#define BNt 64
#define BKt 32
#define A_STRIDE 40
#define B_STRIDE 72
#define A_BYTES  (BMt * A_STRIDE * 2)
#define B_BYTES  (BKt * B_STRIDE * 2)
#define STG_BYTES (A_BYTES + B_BYTES)
#define KT 25

__device__ __forceinline__ void cp_async16(unsigned dst, const void* src, int src_bytes) {
    asm volatile("cp.async.cg.shared.global [%0], [%1], 16, %2;\n"
                 :: "r"(dst), "l"(src), "r"(src_bytes));
}
__device__ __forceinline__ void cp_commit() {
    asm volatile("cp.async.commit_group;\n");
}
__device__ __forceinline__ void cp_wait1() {
    asm volatile("cp.async.wait_group 1;\n");
}
__device__ __forceinline__ void ldmA4(unsigned* r, unsigned addr) {
    asm volatile("ldmatrix.sync.aligned.m8n8.x4.shared.b16 {%0,%1,%2,%3}, [%4];"
                 : "=r"(r[0]), "=r"(r[1]), "=r"(r[2]), "=r"(r[3]) : "r"(addr));
}
__device__ __forceinline__ void ldmBT4(unsigned* r, unsigned addr) {
    asm volatile("ldmatrix.sync.aligned.m8n8.x4.trans.shared.b16 {%0,%1,%2,%3}, [%4];"
                 : "=r"(r[0]), "=r"(r[1]), "=r"(r[2]), "=r"(r[3]) : "r"(addr));
}
__device__ __forceinline__ void mma_f16(float* c, const unsigned* a, const unsigned* b) {
    asm volatile("mma.sync.aligned.m16n8k16.row.col.f32.f16.f16.f32 "
                 "{%0,%1,%2,%3},{%4,%5,%6,%7},{%8,%9},{%0,%1,%2,%3};"
                 : "+f"(c[0]), "+f"(c[1]), "+f"(c[2]), "+f"(c[3])
                 : "r"(a[0]), "r"(a[1]), "r"(a[2]), "r"(a[3]), "r"(b[0]), "r"(b[1]));
}

__device__ __forceinline__ void load_stage(unsigned sbase, int stage, int k0,
                                           int bm, int bn, int t)
{
    unsigned sa = sbase + stage * STG_BYTES;
    unsigned sb = sa + A_BYTES;
    #pragma unroll
    for (int p = 0; p < 2; p++) {
        int li = t + p * 256;
        int row = li >> 2, ch = li & 3;
        int grow = bm + row;
        bool ok = (grow < MP);
        const __half* src = g_Pch + (size_t)(ok ? grow : 0) * 800 + k0 + ch * 8;
        cp_async16(sa + (unsigned)(row * A_STRIDE + ch * 8) * 2, src, ok ? 16 : 0);
    }
    {
        int k = t >> 3, ch = t & 7;
        int col = bn + ch * 8;
        int rem = DMm - col;
        int sz = (rem >= 8) ? 16 : ((rem > 0) ? rem * 2 : 0);
        const __half* src = g_VWh + (size_t)(k0 + k) * DMm + ((col < DMm) ? col : 0);
        cp_async16(sb + (unsigned)(k * B_STRIDE + ch * 8) * 2, src, sz);
    }
}

__global__ __launch_bounds__(256) void k_mma(const float* __restrict__ B3)
{
    __shared__ __align__(16) unsigned char smem[3 * STG_BYTES];
    unsigned sbase = (unsigned)__cvta_generic_to_shared(smem);

    int t = threadIdx.x;
    int w = t >> 5, lane = t & 31;
    int wm = (w & 3) * 32;
    int wn = (w >> 2) * 32;
    int bm = blockIdx.y * BMt, bn = blockIdx.x * BNt;

    float acc[2][4][4];
    #pragma unroll
    for (int mm = 0; mm < 2; mm++)
        #pragma unroll
        for (int nn = 0; nn < 4; nn++)
            #pragma unroll
            for (int q = 0; q < 4; q++) acc[mm][nn][q] = 0.f;

    int arow = wm + (lane & 15);
    int acb  = (lane >> 4) * 8;
    int bkl  = (lane & 7) + (lane & 8);
    int bnl  = wn + ((lane >> 4) * 8);

    load_stage(sbase, 0, 0, bm, bn, t);  cp_commit();
    load_stage(sbase, 1, 32, bm, bn, t); cp_commit();

    for (int kt = 0; kt < KT; kt++) {
        cp_wait1();
        __syncthreads();
        if (kt + 2 < KT) load_stage(sbase, (kt + 2) % 3, (kt + 2) * BKt, bm, bn, t);
        cp_commit();
        unsigned sa = sbase + (kt % 3) * STG_BYTES;
        unsigned sb = sa + A_BYTES;
        #pragma unroll
        for (int ks = 0; ks < 2; ks++) {
            unsigned af[2][4], bf[2][4];
            ldmA4(af[0], sa + (unsigned)((arow)      * A_STRIDE + ks * 16 + acb) * 2);
            ldmA4(af[1], sa + (unsigned)((arow + 16) * A_STRIDE + ks * 16 + acb) * 2);
            ldmBT4(bf[0], sb + (unsigned)((ks * 16 + bkl) * B_STRIDE + bnl) * 2);
            ldmBT4(bf[1], sb + (unsigned)((ks * 16 + bkl) * B_STRIDE + bnl + 16) * 2);
            #pragma unroll
            for (int mm = 0; mm < 2; mm++) {
                mma_f16(acc[mm][0], af[mm], bf[0] + 0);
                mma_f16(acc[mm][1], af[mm], bf[0] + 2);
                mma_f16(acc[mm][2], af[mm], bf[1] + 0);
                mma_f16(acc[mm][3], af[mm], bf[1] + 2);
            }
        }
        __syncthreads();
    }

    int r0 = bm + wm + (lane >> 2);
    int c0 = bn + wn + (lane & 3) * 2;
    #pragma unroll
    for (int mm = 0; mm < 2; mm++) {
        int rbase = r0 + mm * 16;
        #pragma unroll
        for (int nn = 0; nn < 4; nn++) {
            int c = c0 + nn * 8;
            if (c < DMm) {
                float b3a = 2.f * B3[c], b3b = 2.f * B3[c + 1];
                if (rbase < MP) {
                    float2 v = make_float2(acc[mm][nn][0] + b3a, acc[mm][nn][1] + b3b);
                    *(float2*)&g_Sp[(size_t)rbase * DMm + c] = v;
                }
                if (rbase + 8 < MP) {
                    float2 v = make_float2(acc[mm][nn][2] + b3a, acc[mm][nn][3] + b3b);
                    *(float2*)&g_Sp[(size_t)(rbase + 8) * DMm + c] = v;
                }
            }
        }
    }
}

// ---------------- Q_sa on packed rows ----------------
#define QROWS 256
#define QKT   32
__global__ __launch_bounds__(256) void k_qsa(const float* __restrict__ v1w,
                                             const float* __restrict__ v1b,
                                             const float* __restrict__ v2w,
                                             const float* __restrict__ v2b)
{
    __shared__ float sS[QKT][QROWS + 1];
    __shared__ float sW[QKT][48];

    int tid = threadIdx.x;
    int ty = tid >> 2;
    int tx = tid & 3;
    int base = blockIdx.x * QROWS;

    float acc[4][12];
    #pragma unroll
    for (int r = 0; r < 4; r++)
        #pragma unroll
        for (int c = 0; c < 12; c++) acc[r][c] = 0.f;

    for (int k0 = 0; k0 < DMm; k0 += QKT) {
        int TK = DMm - k0; if (TK > QKT) TK = QKT;
        #pragma unroll
        for (int it = 0; it < 8; it++) {
            int idx = tid + it * 256;
            int r = idx >> 3;
            int c4 = idx & 7;
            int k = c4 * 4;
            if (k < TK) {
                int grow = base + r;
                const float* src = g_Sp + (size_t)(grow < MP ? grow : 0) * DMm + k0 + k;
                float4 v = *(const float4*)src;
                sS[k + 0][r] = v.x; sS[k + 1][r] = v.y;
                sS[k + 2][r] = v.z; sS[k + 3][r] = v.w;
            }
        }
        #pragma unroll
        for (int it = 0; it < 6; it++) {
            int idx = tid + it * 256;
            int k = idx / 48, c = idx - k * 48;
            if (k < TK)
                sW[k][c] = v1w[(k0 + k) * 48 + c];
        }
        __syncthreads();
        for (int k = 0; k < TK; k++) {
            float a0 = sS[k][ty * 4 + 0];
            float a1 = sS[k][ty * 4 + 1];
            float a2 = sS[k][ty * 4 + 2];
            float a3 = sS[k][ty * 4 + 3];
            #pragma unroll
            for (int c = 0; c < 12; c++) {
                float wv = sW[k][tx * 12 + c];
                acc[0][c] += a0 * wv;
                acc[1][c] += a1 * wv;
                acc[2][c] += a2 * wv;
                acc[3][c] += a3 * wv;
            }
        }
        __syncthreads();
    }

    float b1[12], w2[12];
    #pragma unroll
    for (int c = 0; c < 12; c++) {
        b1[c] = v1b[tx * 12 + c];
        w2[c] = v2w[tx * 12 + c];
    }
    float vb2 = v2b[0];
    #pragma unroll
    for (int r = 0; r < 4; r++) {
        float part = 0.f;
        #pragma unroll
        for (int c = 0; c < 12; c++)
            part += fmaxf(acc[r][c] + b1[c], 0.f) * w2[c];
        part += __shfl_xor_sync(0xffffffffu, part, 1);
        part += __shfl_xor_sync(0xffffffffu, part, 2);
        int row = base + ty * 4 + r;
        if (tx == 0 && row < MP) g_Qp[row] = part + vb2;
    }
}

// ---------------- scatter packed Sp/Qp to full symmetric output ----------------
__global__ void k_scatter(float* __restrict__ out)
{
    int idx = blockIdx.x * 256 + threadIdx.x;
    if (idx >= MP * DMm) return;
    int pid = idx / DMm;
    int c = idx - pid * DMm;
    float v = g_Sp[idx];
    int2 ij = g_pairs[pid];
    out[(size_t)(ij.x * NN + ij.y) * DMm + c] = v;
    if (ij.x != ij.y)
        out[(size_t)(ij.y * NN + ij.x) * DMm + c] = v;
    if (c == 0) {
        float q = g_Qp[pid];
        out[Q_OFF + ij.x * NN + ij.y] = q;
        if (ij.x != ij.y)
            out[Q_OFF + ij.y * NN + ij.x] = q;
    }
}

// ---------------- tail: copy h, h_full into output ----------------
__global__ void k_tail(float* __restrict__ out, const int* __restrict__ gnn_step)
{
    int idx = blockIdx.x * blockDim.x + threadIdx.x;
    int n = *gnn_step; if (n > GCN_MAX_IT) n = GCN_MAX_IT;
    const float* hbuf = (n & 1) ? g_hB : g_hA;
    if (idx < NN*HIDN) out[H_OFF + idx] = hbuf[idx];
    else if (idx < NN*HIDN + NN*HDd) {
        int j = idx - NN*HIDN;
        out[HF_OFF + j] = g_hfull[j];
    }
}

// ---------------- launcher ----------------
extern "C" void kernel_launch(void* const* d_in, const int* in_sizes, int n_in,
                              void* d_out, int out_size)
{
    const float* x     = (const float*)d_in[0];
    const float* label = (const float*)d_in[1];
    const float* h0    = (const float*)d_in[2];
    const float* w     = (const float*)d_in[3];
    const float* dv    = (const float*)d_in[4];
    const float* l0w   = (const float*)d_in[5];
    const float* l0b   = (const float*)d_in[6];
    const float* l1w   = (const float*)d_in[7];
    const float* l1b   = (const float*)d_in[8];
    const float* l2w   = (const float*)d_in[9];
    const float* l2b   = (const float*)d_in[10];
    const float* l3w   = (const float*)d_in[11];
    const float* l3b   = (const float*)d_in[12];
    const float* l4w   = (const float*)d_in[13];
    const float* l4b   = (const float*)d_in[14];
    const float* l5w   = (const float*)d_in[15];
    const float* l5b   = (const float*)d_in[16];
    const float* W0    = (const float*)d_in[17];
    const float* B0    = (const float*)d_in[18];
    const float* W1    = (const float*)d_in[19];
    const float* B1    = (const float*)d_in[20];
    const float* W3    = (const float*)d_in[21];
    const float* B3    = (const float*)d_in[22];
    const float* v1w   = (const float*)d_in[23];
    const float* v1b   = (const float*)d_in[24];
    const float* v2w   = (const float*)d_in[25];
    const float* v2b   = (const float*)d_in[26];
    const int* gnn_step = (const int*)d_in[27];
    const int* remain   = (const int*)d_in[29];
    float* out = (float*)d_out;

    k_prep<<<NN, 128>>>(x, label, h0, w, dv, l0w, l0b, l1w, l1b, l2b, l3b, l4w, l4b, l5w, l5b);
    k_pairs<<<(MP + 255)/256, 256>>>();
    for (int it = 0; it < GCN_MAX_IT; it++)
        k_gcn<<<NN, HIDN>>>(w, l2w, l3w, gnn_step, it);
    k_hfull<<<NN, 128>>>(x, label, remain, gnn_step);
    k_gct<<<KK, HDd>>>(label);
    k_lg<<<NN, HDd>>>(label);
    k_wsum<<<(HDd*DMm + 255)/256, 256>>>(W0, W1);
    k_proj<<<NN, 128>>>(W0, B0, B1);
    dim3 guv(NN, NHh);
    k_uv<<<guv, 256>>>();
    k_expuv<<<100, 256>>>();
    k_vw<<<NHh*NN, 128>>>(W3);
    k_prob<<<MP, 256>>>();
    dim3 gs(8, MTILE);
    k_mma<<<gs, 256>>>(B3);
    k_qsa<<<(MP + QROWS - 1)/QROWS, 256>>>(v1w, v1b, v2w, v2b);
    k_scatter<<<(MP*DMm + 255)/256, 256>>>(out);
    k_tail<<<(NN*HIDN + NN*HDd + 255)/256, 256>>>(out, gnn_step);
}